// round 16
// baseline (speedup 1.0000x reference)
#include <cuda_runtime.h>
#include <cuda_bf16.h>
#include <cstdint>

// Algebraic collapse (alpha=1): exp(lse) = sum_r exp(ln(x_r+1)+k_r+5) = sum_r (x_r+1)e^{k_r+5}
// -> out[m,co] = sum_r A[m,r]*W''[r,co] + C[co],  W'' = e^{k+5}-dw,
//    C = sum_r e^{k_r+5} - dx*sum_r k_r + bias.
// GEMM M=6272(=98x64), N=64, K=288(=18 k16 steps) via mma.sync.m16n8k16 bf16.
// R16: SINGLE kernel, no cross-block deps. Every block computes W''/C itself
// (36 MUFU/thread ~ 0.6us, runs in parallel on all SMs and overlaps the
// scattered A-staging latency). k loads are warp-coalesced (co = tid&63).
// One launch -> one T_ovh, no prep kernel, no launch gap.

__device__ __forceinline__ uint32_t smem_u32(const void* p) {
    uint32_t a;
    asm("{ .reg .u64 t; cvta.to.shared.u64 t, %1; cvt.u32.u64 %0, t; }" : "=r"(a) : "l"(p));
    return a;
}
__device__ __forceinline__ void ldmx4(uint32_t* r, uint32_t addr) {
    asm volatile("ldmatrix.sync.aligned.m8n8.x4.shared.b16 {%0,%1,%2,%3}, [%4];"
                 : "=r"(r[0]), "=r"(r[1]), "=r"(r[2]), "=r"(r[3]) : "r"(addr));
}
__device__ __forceinline__ void mma16816(float* d, const uint32_t* a,
                                         uint32_t b0, uint32_t b1) {
    asm volatile(
        "mma.sync.aligned.m16n8k16.row.col.f32.bf16.bf16.f32 "
        "{%0,%1,%2,%3}, {%4,%5,%6,%7}, {%8,%9}, {%0,%1,%2,%3};"
        : "+f"(d[0]), "+f"(d[1]), "+f"(d[2]), "+f"(d[3])
        : "r"(a[0]), "r"(a[1]), "r"(a[2]), "r"(a[3]), "r"(b0), "r"(b1));
}
__device__ __forceinline__ uint32_t pack_bf16x2(float a, float b) {
    __nv_bfloat162 t = __floats2bfloat162_rn(a, b);
    return *reinterpret_cast<uint32_t*>(&t);
}

constexpr int STRB  = 592;                 // 37*16B rows: conflict-free ldmatrix
constexpr int OFF_A = 0;                   // 64*592 = 37888 ; sD aliases this later
constexpr int OFF_B = 37888;               // 64*592
constexpr int OFF_C = 75776;               // 64 floats
constexpr int OFF_R = 76032;               // reduce scratch: 2*8*64 floats = 4096
constexpr int SMEMB = OFF_R + 4096;        // 80128
constexpr int CNT   = 512;                 // 16 warps

__global__ void __launch_bounds__(CNT) fused_conv_kernel(
    const float* __restrict__ x, const float* __restrict__ k,
    const float* __restrict__ bias,
    const float* __restrict__ dxp, const float* __restrict__ dwp,
    float* __restrict__ out)
{
    extern __shared__ __align__(16) char sm[];
    const uint32_t smb = smem_u32(sm);
    const int tid  = threadIdx.x;
    const int wid  = tid >> 5;
    const int lane = tid & 31;
    const int t    = blockIdx.x;             // M-tile, 98 tiles of 64 rows

    // ---- Phase 1: stage A from fp32 x (inline bf16 convert), block-local ----
    {
        const int row   = tid >> 3;          // 0..63
        const int lane8 = tid & 7;
        int m = t * 64 + row;
        int b = m / 784, rem = m - b * 784;
        int h = rem / 28, w = rem - h * 28;
        const float* xb = x + (size_t)b * 32 * 784;
        char* dA = sm + OFF_A + row * STRB;
        #pragma unroll
        for (int i = 0; i < 5; i++) {
            int c36 = lane8 + 8 * i;
            if (c36 < 36) {
                int seg = c36 >> 2, c8 = c36 & 3;          // 8 cins per 16B chunk
                int kh = seg / 3, kw = seg - kh * 3;
                int ir = h + kh - 1, ic = w + kw - 1;
                uint4 v = make_uint4(0, 0, 0, 0);
                if ((unsigned)ir < 28u && (unsigned)ic < 28u) {
                    const float* p = xb + (size_t)(c8 * 8) * 784 + ir * 28 + ic;
                    v.x = pack_bf16x2(p[0 * 784], p[1 * 784]);
                    v.y = pack_bf16x2(p[2 * 784], p[3 * 784]);
                    v.z = pack_bf16x2(p[4 * 784], p[5 * 784]);
                    v.w = pack_bf16x2(p[6 * 784], p[7 * 784]);
                }
                *reinterpret_cast<uint4*>(dA + c36 * 16) = v;
            }
        }
    }

    // ---- Phase 2: in-block weight transform W'' = exp(k+5)-dw -> sB (bf16) ----
    // thread: co = tid&63 (warp-coalesced k reads), g = tid>>6; r = g + 8*j.
    {
        const int co = tid & 63;
        const int g  = tid >> 6;             // 0..7
        const float dw = dwp[0];
        __nv_bfloat16* sBrow = reinterpret_cast<__nv_bfloat16*>(sm + OFF_B + co * STRB);
        float pse = 0.f, psk = 0.f;
        #pragma unroll
        for (int j = 0; j < 36; j++) {
            int r = g + 8 * j;               // covers 0..287 exactly over g,j
            float kv = __ldg(&k[r * 64 + co]);
            float e  = __expf(kv + 5.0f);
            sBrow[r] = __float2bfloat16(e - dw);
            pse += e; psk += kv;
        }
        float* red = reinterpret_cast<float*>(sm + OFF_R);
        red[g * 64 + co]       = pse;        // [0][g][co]
        red[512 + g * 64 + co] = psk;        // [1][g][co]
    }
    __syncthreads();

    // ---- C[co] (warps 0-1 while others proceed to MMA setup) ----
    float* sC = reinterpret_cast<float*>(sm + OFF_C);
    if (tid < 64) {
        const float* red = reinterpret_cast<const float*>(sm + OFF_R);
        float SE = 0.f, SK = 0.f;
        #pragma unroll
        for (int g = 0; g < 8; g++) { SE += red[g * 64 + tid]; SK += red[512 + g * 64 + tid]; }
        sC[tid] = SE - dxp[0] * SK + bias[tid];
    }

    // ---- Phase 3: 16 warps = 4(M) x 4(N); warp tile 16M x 16N; 2 K-chains ----
    const int wm = (wid & 3) * 16;
    const int wn = (wid >> 2) * 16;
    uint32_t aAddr = smb + OFF_A + (uint32_t)(wm + (lane & 15)) * STRB + (lane >> 4) * 16;
    uint32_t bAddr = smb + OFF_B + (uint32_t)(wn + (lane & 15)) * STRB + (lane >> 4) * 16;

    float acc0[8], acc1[8];
    #pragma unroll
    for (int i = 0; i < 8; i++) { acc0[i] = 0.f; acc1[i] = 0.f; }

    #pragma unroll
    for (int ks = 0; ks < 9; ks++) {
        uint32_t a0[4], b0[4], a1[4], b1[4];
        ldmx4(a0, aAddr + ks * 32);
        ldmx4(b0, bAddr + ks * 32);
        ldmx4(a1, aAddr + (ks + 9) * 32);
        ldmx4(b1, bAddr + (ks + 9) * 32);
        mma16816(acc0 + 0, a0, b0[0], b0[2]);
        mma16816(acc0 + 4, a0, b0[1], b0[3]);
        mma16816(acc1 + 0, a1, b1[0], b1[2]);
        mma16816(acc1 + 4, a1, b1[1], b1[3]);
    }
    #pragma unroll
    for (int i = 0; i < 8; i++) acc0[i] += acc1[i];

    // ---- Phase 4: frags -> smem [co][j] (aliases A), coalesced STG ----
    __syncthreads();                          // ldmatrix reads done; sC written
    float* sD = reinterpret_cast<float*>(sm + OFF_A);   // stride 65
    {
        const int row  = lane >> 2;
        const int colp = (lane & 3) * 2;
        int j0 = wm + row, j1 = j0 + 8;
        #pragma unroll
        for (int jj = 0; jj < 2; jj++) {
            int co = wn + jj * 8 + colp;
            sD[(co    ) * 65 + j0] = acc0[jj * 4 + 0];
            sD[(co + 1) * 65 + j0] = acc0[jj * 4 + 1];
            sD[(co    ) * 65 + j1] = acc0[jj * 4 + 2];
            sD[(co + 1) * 65 + j1] = acc0[jj * 4 + 3];
        }
    }
    __syncthreads();
    {
        int m0 = t * 64;
        int b0 = m0 / 784;
        int jb = (b0 + 1) * 784 - m0;        // j >= jb -> next batch image
        #pragma unroll
        for (int i = 0; i < 8; i++) {
            int idx = i * CNT + tid;
            int co  = idx >> 6;
            int j   = idx & 63;
            int b   = b0 + (j >= jb ? 1 : 0);
            int hw  = m0 + j - b * 784;
            out[((size_t)(b * 64 + co)) * 784 + hw] = sD[co * 65 + j] + sC[co];
        }
    }
}

// ---------------- launch: ONE kernel ----------------
extern "C" void kernel_launch(void* const* d_in, const int* in_sizes, int n_in,
                              void* d_out, int out_size)
{
    (void)in_sizes; (void)n_in; (void)out_size;
    const float* x    = (const float*)d_in[0];
    const float* k    = (const float*)d_in[1];
    const float* bias = (const float*)d_in[2];
    const float* dx   = (const float*)d_in[3];
    const float* dw   = (const float*)d_in[4];
    float* out        = (float*)d_out;

    cudaFuncSetAttribute(fused_conv_kernel,
                         cudaFuncAttributeMaxDynamicSharedMemorySize, SMEMB);

    fused_conv_kernel<<<98, CNT, SMEMB>>>(x, k, bias, dx, dw, out);
}